// round 16
// baseline (speedup 1.0000x reference)
#include <cuda_runtime.h>
#include <cuda_bf16.h>
#include <math.h>

// Problem constants
#define HIDDEN    2560
#define NUM_HEADS 8
#define HEAD_DIM  512
#define SEQ       32768
#define QROWS     (NUM_HEADS * HEAD_DIM)   // 4096
#define SCALE     0.04419417382415922f     // 1/sqrt(512)

#define CHUNK     64                       // keys per attention block
#define NCHUNK    (SEQ / CHUNK)            // 512 blocks
#define NSUB      4                        // sub-tiles per chunk
#define SUBK      16                       // keys per sub-tile

// ------------------------- device scratch (no allocs allowed) ---------------
__device__ __align__(16) float g_q[QROWS];
__device__ float g_pl[NCHUNK * NUM_HEADS];          // per-chunk expsum (m == 0)
__device__ __align__(16) float g_pacc[(size_t)NCHUNK * QROWS];    // 8 MB
__device__ __align__(16) float g_attn[QROWS];

// ------------------------- helpers ------------------------------------------
__device__ __forceinline__ float warp_sum(float v) {
    #pragma unroll
    for (int o = 16; o; o >>= 1) v += __shfl_xor_sync(0xffffffffu, v, o);
    return v;
}
__device__ __forceinline__ float4 ldcs4(const float* p) {
    return __ldcs(reinterpret_cast<const float4*>(p));
}

// ------------------------- kernel 1: fused QKV GEMV --------------------------
// 2560 blocks x 128 thr. K/V written directly into kv_full at current_pos
// (reference's dynamic_update_slice; idempotent across graph replays).
__global__ void __launch_bounds__(128)
qkv_gemv(const float* __restrict__ x,
         const float* __restrict__ wq,
         const float* __restrict__ wk,
         const float* __restrict__ wv,
         float* __restrict__ kv_full,
         const int* __restrict__ cur_pos) {
    const int warp = threadIdx.x >> 5, lane = threadIdx.x & 31;
    const int gw = blockIdx.x * 4 + warp;
    const int r = gw >> 1, half = gw & 1;
    const int cp = cur_pos[0];

    const float* w;
    float* outp;
    if (r < QROWS) {
        w = wq + (size_t)r * HIDDEN;
        outp = g_q + r;
    } else if (r < QROWS + 512) {
        w = wk + (size_t)(r - QROWS) * HIDDEN;
        outp = kv_full + (size_t)cp * HEAD_DIM + (r - QROWS);
    } else {
        w = wv + (size_t)(r - QROWS - 512) * HIDDEN;
        outp = kv_full + (size_t)SEQ * HEAD_DIM + (size_t)cp * HEAD_DIM + (r - QROWS - 512);
    }

    const float4* w4 = reinterpret_cast<const float4*>(w);
    const float4* x4 = reinterpret_cast<const float4*>(x);
    const int base = half * (HIDDEN / 8);      // 320 float4 per half
    float s = 0.f;
    #pragma unroll
    for (int i = 0; i < HIDDEN / 8 / 32; i++) {    // 10 iterations
        float4 a = __ldcs(w4 + base + i * 32 + lane);
        float4 b = x4[base + i * 32 + lane];
        s += a.x * b.x + a.y * b.y + a.z * b.z + a.w * b.w;
    }
    s = warp_sum(s);

    __shared__ float part[4];
    if (lane == 0) part[warp] = s;
    __syncthreads();
    if (lane == 0 && half == 0)
        *outp = part[warp] + part[warp + 1];
}

// ------------------------- kernel 2: warp-specialized flash-decode -----------
// 512 blocks x 256 threads. Warps 0-3: scores (K stream) producer.
// Warps 4-7: P@V (V stream) consumer. 4 sub-tiles of 16 keys, double-buffered
// probs, named-barrier handshake. m == 0 softmax (scores are O(1)):
// partials directly summable, no Phase B, no PV smem combine.
__global__ void __launch_bounds__(256)
attn_chunk(const float* __restrict__ kv_full) {
    __shared__ __align__(16) float qs[QROWS];          // 16 KB
    __shared__ float pb[2][NUM_HEADS][SUBK];           // double-buffered probs
    __shared__ float lsc[4][NUM_HEADS];                // per-score-warp l partials

    const int tid = threadIdx.x;
    const int warp = tid >> 5, lane = tid & 31;
    const int j0 = blockIdx.x * CHUNK;

    for (int i = tid; i < QROWS; i += 256) qs[i] = g_q[i];
    __syncthreads();

    if (warp < 4) {
        // =================== score side (producer) ===================
        float lacc[NUM_HEADS];
        #pragma unroll
        for (int h = 0; h < NUM_HEADS; h++) lacc[h] = 0.f;

        for (int s = 0; s < NSUB; s++) {
            const int b = s & 1;
            if (s >= 2) asm volatile("bar.sync %0, 256;" :: "r"(4 + b));  // EMPTY[b]

            const int jj = s * SUBK + warp * 4;
            const float* kbase = kv_full + (size_t)(j0 + jj) * HEAD_DIM;

            float acc[NUM_HEADS][4];
            #pragma unroll
            for (int h = 0; h < NUM_HEADS; h++)
                #pragma unroll
                for (int t = 0; t < 4; t++) acc[h][t] = 0.f;

            #pragma unroll
            for (int i = 0; i < 4; i++) {
                int d = i * 128 + lane * 4;
                float4 kv0 = ldcs4(kbase + 0 * HEAD_DIM + d);
                float4 kv1 = ldcs4(kbase + 1 * HEAD_DIM + d);
                float4 kv2 = ldcs4(kbase + 2 * HEAD_DIM + d);
                float4 kv3 = ldcs4(kbase + 3 * HEAD_DIM + d);
                #pragma unroll
                for (int h = 0; h < NUM_HEADS; h++) {
                    float4 qv = *reinterpret_cast<const float4*>(qs + h * HEAD_DIM + d);
                    acc[h][0] += qv.x * kv0.x + qv.y * kv0.y + qv.z * kv0.z + qv.w * kv0.w;
                    acc[h][1] += qv.x * kv1.x + qv.y * kv1.y + qv.z * kv1.z + qv.w * kv1.w;
                    acc[h][2] += qv.x * kv2.x + qv.y * kv2.y + qv.z * kv2.z + qv.w * kv2.w;
                    acc[h][3] += qv.x * kv3.x + qv.y * kv3.y + qv.z * kv3.z + qv.w * kv3.w;
                }
            }
            #pragma unroll
            for (int h = 0; h < NUM_HEADS; h++) {
                #pragma unroll
                for (int t = 0; t < 4; t++) {
                    float sc = warp_sum(acc[h][t]);
                    float e = __expf(sc * SCALE);   // uniform across lanes
                    lacc[h] += e;
                    if (lane == 0) pb[b][h][warp * 4 + t] = e;
                }
            }
            asm volatile("bar.arrive %0, 256;" :: "r"(2 + b));            // FULL[b]
        }
        // combine l over the 4 score warps; lacc uniform across lanes
        if (lane < NUM_HEADS) lsc[warp][lane] = lacc[lane];
        asm volatile("bar.sync 6, 128;");                                 // score warps only
        if (warp == 0 && lane < NUM_HEADS)
            g_pl[blockIdx.x * NUM_HEADS + lane] =
                lsc[0][lane] + lsc[1][lane] + lsc[2][lane] + lsc[3][lane];
    } else {
        // =================== PV side (consumer) ===================
        const int t = tid - 128;                 // 0..127
        const int d = t * 4;                     // unique d-slice, no combine needed
        const float* vbase = kv_full + (size_t)SEQ * HEAD_DIM
                           + (size_t)j0 * HEAD_DIM + d;

        float4 acc4[NUM_HEADS];
        #pragma unroll
        for (int h = 0; h < NUM_HEADS; h++) acc4[h] = make_float4(0.f, 0.f, 0.f, 0.f);

        for (int s = 0; s < NSUB; s++) {
            const int b = s & 1;
            asm volatile("bar.sync %0, 256;" :: "r"(2 + b));              // FULL[b]

            const float* vrow = vbase + (size_t)s * SUBK * HEAD_DIM;
            #pragma unroll
            for (int jj = 0; jj < SUBK; jj++) {
                float4 vv = ldcs4(vrow);
                vrow += HEAD_DIM;
                #pragma unroll
                for (int h = 0; h < NUM_HEADS; h++) {
                    float pw = pb[b][h][jj];
                    acc4[h].x = fmaf(pw, vv.x, acc4[h].x);
                    acc4[h].y = fmaf(pw, vv.y, acc4[h].y);
                    acc4[h].z = fmaf(pw, vv.z, acc4[h].z);
                    acc4[h].w = fmaf(pw, vv.w, acc4[h].w);
                }
            }
            asm volatile("bar.arrive %0, 256;" :: "r"(4 + b));            // EMPTY[b]
        }
        float* o = g_pacc + (size_t)blockIdx.x * QROWS;
        #pragma unroll
        for (int h = 0; h < NUM_HEADS; h++)
            *reinterpret_cast<float4*>(o + h * HEAD_DIM + d) = acc4[h];
    }
}

// ------------------------- kernel 3: unweighted reduce + normalize -----------
// 128 blocks x 256 thr. Block b: head h=b/16, 8 float4 outputs (32 floats).
// m == 0: out = (sum of partials over 512 chunks) / (sum of per-chunk l).
__global__ void __launch_bounds__(256)
reduce_final() {
    const int b  = blockIdx.x;
    const int h  = b >> 4;
    const int f4base = b * 8;                  // float4 index into QROWS/4 = 1024

    __shared__ float red[8];
    __shared__ float sInv;
    __shared__ __align__(16) float4 part[32][8];
    const int lane = threadIdx.x & 31, warp = threadIdx.x >> 5;

    // L = total expsum for head h over 512 chunks (2 per thread)
    float l = g_pl[(threadIdx.x * 2) * NUM_HEADS + h]
            + g_pl[(threadIdx.x * 2 + 1) * NUM_HEADS + h];
    l = warp_sum(l);
    if (lane == 0) red[warp] = l;
    __syncthreads();
    if (threadIdx.x == 0) {
        float L = 0.f;
        #pragma unroll
        for (int i = 0; i < 8; i++) L += red[i];
        sInv = 1.f / L;
    }
    __syncthreads();

    const int f4o = threadIdx.x & 7;
    const int cg  = threadIdx.x >> 3;          // 0..31, 16 chunks each
    const float4* pacc4 = reinterpret_cast<const float4*>(g_pacc);

    float4 s = make_float4(0.f, 0.f, 0.f, 0.f);
    #pragma unroll
    for (int k = 0; k < 16; k++) {
        int c = cg * 16 + k;
        float4 v = pacc4[(size_t)c * (QROWS / 4) + f4base + f4o];
        s.x += v.x; s.y += v.y; s.z += v.z; s.w += v.w;
    }
    part[cg][f4o] = s;
    __syncthreads();
    if (threadIdx.x < 8) {
        float4 acc = part[0][threadIdx.x];
        #pragma unroll
        for (int g = 1; g < 32; g++) {
            float4 v = part[g][threadIdx.x];
            acc.x += v.x; acc.y += v.y; acc.z += v.z; acc.w += v.w;
        }
        float inv = sInv;
        acc.x *= inv; acc.y *= inv; acc.z *= inv; acc.w *= inv;
        reinterpret_cast<float4*>(g_attn)[f4base + threadIdx.x] = acc;
    }
}

// ------------------------- kernel 4: output GEMV -----------------------------
// 1280 blocks x 128 thr (4 warps). Unit = half-row.
__global__ void __launch_bounds__(128)
wo_gemv(const float* __restrict__ wo, float* __restrict__ out) {
    const int warp = threadIdx.x >> 5, lane = threadIdx.x & 31;
    const int gw = blockIdx.x * 4 + warp;
    const int r = gw >> 1, half = gw & 1;

    const float4* w4 = reinterpret_cast<const float4*>(wo + (size_t)r * QROWS);
    const float4* a4 = reinterpret_cast<const float4*>(g_attn);
    const int base = half * (QROWS / 8);       // 512 float4 per half
    float s = 0.f;
    #pragma unroll
    for (int i = 0; i < QROWS / 8 / 32; i++) {     // 16 iterations
        float4 a = __ldcs(w4 + base + i * 32 + lane);
        float4 b = a4[base + i * 32 + lane];
        s += a.x * b.x + a.y * b.y + a.z * b.z + a.w * b.w;
    }
    s = warp_sum(s);

    __shared__ float part[4];
    if (lane == 0) part[warp] = s;
    __syncthreads();
    if (lane == 0 && half == 0)
        out[r] = part[warp] + part[warp + 1];
}

// ------------------------- launch -------------------------------------------
extern "C" void kernel_launch(void* const* d_in, const int* in_sizes, int n_in,
                              void* d_out, int out_size) {
    const float* x       = (const float*)d_in[0];
    // d_in[1] = kv_sliding (unused by reference math)
    float*       kv_full = (float*)d_in[2];
    const float* wq      = (const float*)d_in[3];
    const float* wk      = (const float*)d_in[4];
    const float* wv      = (const float*)d_in[5];
    const float* wo      = (const float*)d_in[6];
    const int*   curpos  = (const int*)d_in[7];
    // d_in[8] = ring_pos (unused)
    float* out = (float*)d_out;

    qkv_gemv<<<2560, 128>>>(x, wq, wk, wv, kv_full, curpos);
    attn_chunk<<<NCHUNK, 256>>>(kv_full);
    reduce_final<<<128, 256>>>();
    wo_gemv<<<1280, 128>>>(wo, out);
}

// round 17
// speedup vs baseline: 1.0642x; 1.0642x over previous
#include <cuda_runtime.h>
#include <cuda_bf16.h>
#include <math.h>

// Problem constants
#define HIDDEN    2560
#define NUM_HEADS 8
#define HEAD_DIM  512
#define SEQ       32768
#define QROWS     (NUM_HEADS * HEAD_DIM)   // 4096
#define SCALE     0.04419417382415922f     // 1/sqrt(512)

#define CHUNK     64                       // keys per attention block
#define NCHUNK    (SEQ / CHUNK)            // 512 blocks

// ------------------------- device scratch (no allocs allowed) ---------------
__device__ __align__(16) float g_q[QROWS];
__device__ float g_pm[NCHUNK * NUM_HEADS];          // per-chunk max
__device__ float g_pl[NCHUNK * NUM_HEADS];          // per-chunk expsum
__device__ __align__(16) float g_pacc[(size_t)NCHUNK * QROWS];    // 8 MB
__device__ __align__(16) float g_attn[QROWS];

// ------------------------- helpers ------------------------------------------
__device__ __forceinline__ float warp_sum(float v) {
    #pragma unroll
    for (int o = 16; o; o >>= 1) v += __shfl_xor_sync(0xffffffffu, v, o);
    return v;
}
__device__ __forceinline__ float warp_max(float v) {
    #pragma unroll
    for (int o = 16; o; o >>= 1) v = fmaxf(v, __shfl_xor_sync(0xffffffffu, v, o));
    return v;
}
__device__ __forceinline__ float4 ldcs4(const float* p) {
    return __ldcs(reinterpret_cast<const float4*>(p));
}

// ------------------------- kernel 1: fused QKV GEMV (warp-per-row) -----------
// 1280 blocks x 128 thr (4 warps); warp handles one full row (20 float4/lane,
// 320B in flight). K/V rows written directly into kv_full at current_pos
// (reference's dynamic_update_slice; idempotent across graph replays).
__global__ void __launch_bounds__(128)
qkv_gemv(const float* __restrict__ x,
         const float* __restrict__ wq,
         const float* __restrict__ wk,
         const float* __restrict__ wv,
         float* __restrict__ kv_full,
         const int* __restrict__ cur_pos) {
    const int warp = threadIdx.x >> 5, lane = threadIdx.x & 31;
    const int r = blockIdx.x * 4 + warp;
    const int cp = cur_pos[0];

    const float* w;
    float* outp;
    if (r < QROWS) {
        w = wq + (size_t)r * HIDDEN;
        outp = g_q + r;
    } else if (r < QROWS + 512) {
        w = wk + (size_t)(r - QROWS) * HIDDEN;
        outp = kv_full + (size_t)cp * HEAD_DIM + (r - QROWS);
    } else {
        w = wv + (size_t)(r - QROWS - 512) * HIDDEN;
        outp = kv_full + (size_t)SEQ * HEAD_DIM + (size_t)cp * HEAD_DIM + (r - QROWS - 512);
    }

    const float4* w4 = reinterpret_cast<const float4*>(w);
    const float4* x4 = reinterpret_cast<const float4*>(x);
    float s = 0.f;
    #pragma unroll
    for (int i = 0; i < HIDDEN / 4 / 32; i++) {    // 20 iterations
        float4 a = __ldcs(w4 + i * 32 + lane);
        float4 b = x4[i * 32 + lane];
        s += a.x * b.x + a.y * b.y + a.z * b.z + a.w * b.w;
    }
    s = warp_sum(s);
    if (lane == 0) *outp = s;
}

// ------------------------- kernel 2: fused flash-decode chunk ----------------
// 512 blocks x 256 threads. Each block: 64 keys. (R15 exact — measured best)
__global__ void __launch_bounds__(256)
attn_chunk(const float* __restrict__ kv_full) {
    __shared__ __align__(16) float qs[QROWS];          // 16 KB (reused as combine buf)
    __shared__ float p[NUM_HEADS][CHUNK];              // scores -> probs, 2 KB

    for (int i = threadIdx.x; i < QROWS; i += 256) qs[i] = g_q[i];
    __syncthreads();

    const int warp = threadIdx.x >> 5, lane = threadIdx.x & 31;
    const int j0 = blockIdx.x * CHUNK;

    // ---- Phase A: scores (8 warps x 8 keys; 4 keys concurrently per warp) ----
    #pragma unroll
    for (int g = 0; g < 2; g++) {
        const int jj = warp * 8 + g * 4;
        const float* kbase = kv_full + (size_t)(j0 + jj) * HEAD_DIM;

        float acc[NUM_HEADS][4];
        #pragma unroll
        for (int h = 0; h < NUM_HEADS; h++)
            #pragma unroll
            for (int t = 0; t < 4; t++) acc[h][t] = 0.f;

        #pragma unroll
        for (int i = 0; i < 4; i++) {
            int d = i * 128 + lane * 4;
            float4 kv0 = ldcs4(kbase + 0 * HEAD_DIM + d);
            float4 kv1 = ldcs4(kbase + 1 * HEAD_DIM + d);
            float4 kv2 = ldcs4(kbase + 2 * HEAD_DIM + d);
            float4 kv3 = ldcs4(kbase + 3 * HEAD_DIM + d);
            #pragma unroll
            for (int h = 0; h < NUM_HEADS; h++) {
                float4 qv = *reinterpret_cast<const float4*>(qs + h * HEAD_DIM + d);
                acc[h][0] += qv.x * kv0.x + qv.y * kv0.y + qv.z * kv0.z + qv.w * kv0.w;
                acc[h][1] += qv.x * kv1.x + qv.y * kv1.y + qv.z * kv1.z + qv.w * kv1.w;
                acc[h][2] += qv.x * kv2.x + qv.y * kv2.y + qv.z * kv2.z + qv.w * kv2.w;
                acc[h][3] += qv.x * kv3.x + qv.y * kv3.y + qv.z * kv3.z + qv.w * kv3.w;
            }
        }
        #pragma unroll
        for (int h = 0; h < NUM_HEADS; h++) {
            #pragma unroll
            for (int t = 0; t < 4; t++) {
                float s = warp_sum(acc[h][t]);
                if (lane == 0) p[h][jj + t] = s * SCALE;
            }
        }
    }
    __syncthreads();

    // ---- Phase B: local softmax stats (warp h handles head h) ----
    {
        const int h = warp;
        float a = p[h][lane];
        float b = p[h][lane + 32];
        float m = warp_max(fmaxf(a, b));
        float ea = __expf(a - m);
        float eb = __expf(b - m);
        float l = warp_sum(ea + eb);
        p[h][lane]      = ea;
        p[h][lane + 32] = eb;
        if (lane == 0) {
            g_pm[blockIdx.x * NUM_HEADS + h] = m;
            g_pl[blockIdx.x * NUM_HEADS + h] = l;
        }
    }
    __syncthreads();

    // ---- Phase C: P @ V partial (float4, jj split across thread halves) ----
    const int half = threadIdx.x >> 7;          // 0 or 1
    const int t    = threadIdx.x & 127;
    const int d    = t * 4;
    const int jbase = half * 32;
    const float* vrow = kv_full + (size_t)SEQ * HEAD_DIM
                      + (size_t)(j0 + jbase) * HEAD_DIM + d;

    float4 acc4[NUM_HEADS];
    #pragma unroll
    for (int h = 0; h < NUM_HEADS; h++) acc4[h] = make_float4(0.f, 0.f, 0.f, 0.f);

    #pragma unroll 8
    for (int jj = 0; jj < 32; jj++) {
        float4 vv = ldcs4(vrow);
        vrow += HEAD_DIM;
        #pragma unroll
        for (int h = 0; h < NUM_HEADS; h++) {
            float pw = p[h][jbase + jj];
            acc4[h].x = fmaf(pw, vv.x, acc4[h].x);
            acc4[h].y = fmaf(pw, vv.y, acc4[h].y);
            acc4[h].z = fmaf(pw, vv.z, acc4[h].z);
            acc4[h].w = fmaf(pw, vv.w, acc4[h].w);
        }
    }

    // combine halves via smem (reuse qs: 128 t x 8 h x float4 = 16 KB)
    __syncthreads();
    float4* cb = reinterpret_cast<float4*>(qs);
    if (half == 1) {
        #pragma unroll
        for (int h = 0; h < NUM_HEADS; h++) cb[h * 128 + t] = acc4[h];
    }
    __syncthreads();
    if (half == 0) {
        float* o = g_pacc + (size_t)blockIdx.x * QROWS;
        #pragma unroll
        for (int h = 0; h < NUM_HEADS; h++) {
            float4 b = cb[h * 128 + t];
            float4 r = acc4[h];
            r.x += b.x; r.y += b.y; r.z += b.z; r.w += b.w;
            *reinterpret_cast<float4*>(o + h * HEAD_DIM + d) = r;
        }
    }
}

// ------------------------- kernel 3: single-pass weighted reduce -------------
// 128 blocks x 256 thr. Block b: head h=b/16, 8 float4 outputs (32 floats).
__global__ void __launch_bounds__(256)
reduce_final() {
    const int b  = blockIdx.x;
    const int h  = b >> 4;
    const int f4base = b * 8;                  // float4 index into QROWS/4 = 1024

    __shared__ float red[8];
    __shared__ float sM, sL;
    __shared__ float w[NCHUNK];                // 2 KB
    __shared__ __align__(16) float4 part[32][8];
    const int lane = threadIdx.x & 31, warp = threadIdx.x >> 5;

    // global softmax stats for head h over 512 chunks (2 per thread)
    float m0 = g_pm[(threadIdx.x * 2) * NUM_HEADS + h];
    float m1 = g_pm[(threadIdx.x * 2 + 1) * NUM_HEADS + h];
    float m = warp_max(fmaxf(m0, m1));
    if (lane == 0) red[warp] = m;
    __syncthreads();
    if (threadIdx.x == 0) {
        float M = red[0];
        #pragma unroll
        for (int i = 1; i < 8; i++) M = fmaxf(M, red[i]);
        sM = M;
    }
    __syncthreads();
    float e0 = __expf(m0 - sM);
    float e1 = __expf(m1 - sM);
    float l = g_pl[(threadIdx.x * 2) * NUM_HEADS + h] * e0
            + g_pl[(threadIdx.x * 2 + 1) * NUM_HEADS + h] * e1;
    l = warp_sum(l);
    __syncthreads();
    if (lane == 0) red[warp] = l;
    __syncthreads();
    if (threadIdx.x == 0) {
        float L = 0.f;
        #pragma unroll
        for (int i = 0; i < 8; i++) L += red[i];
        sL = L;
    }
    __syncthreads();
    w[threadIdx.x * 2]     = e0 / sL;
    w[threadIdx.x * 2 + 1] = e1 / sL;
    __syncthreads();

    const int f4o = threadIdx.x & 7;
    const int cg  = threadIdx.x >> 3;          // 0..31
    const float4* pacc4 = reinterpret_cast<const float4*>(g_pacc);

    float4 s = make_float4(0.f, 0.f, 0.f, 0.f);
    #pragma unroll
    for (int k = 0; k < 16; k++) {
        int c = cg * 16 + k;
        float4 v = pacc4[(size_t)c * (QROWS / 4) + f4base + f4o];
        float wt = w[c];
        s.x = fmaf(wt, v.x, s.x);
        s.y = fmaf(wt, v.y, s.y);
        s.z = fmaf(wt, v.z, s.z);
        s.w = fmaf(wt, v.w, s.w);
    }
    part[cg][f4o] = s;
    __syncthreads();
    if (threadIdx.x < 8) {
        float4 acc = part[0][threadIdx.x];
        #pragma unroll
        for (int g = 1; g < 32; g++) {
            float4 v = part[g][threadIdx.x];
            acc.x += v.x; acc.y += v.y; acc.z += v.z; acc.w += v.w;
        }
        reinterpret_cast<float4*>(g_attn)[f4base + threadIdx.x] = acc;
    }
}

// ------------------------- kernel 4: output GEMV -----------------------------
// 1280 blocks x 128 thr (4 warps). Unit = half-row.
__global__ void __launch_bounds__(128)
wo_gemv(const float* __restrict__ wo, float* __restrict__ out) {
    const int warp = threadIdx.x >> 5, lane = threadIdx.x & 31;
    const int gw = blockIdx.x * 4 + warp;
    const int r = gw >> 1, half = gw & 1;

    const float4* w4 = reinterpret_cast<const float4*>(wo + (size_t)r * QROWS);
    const float4* a4 = reinterpret_cast<const float4*>(g_attn);
    const int base = half * (QROWS / 8);       // 512 float4 per half
    float s = 0.f;
    #pragma unroll
    for (int i = 0; i < QROWS / 8 / 32; i++) {     // 16 iterations
        float4 a = __ldcs(w4 + base + i * 32 + lane);
        float4 b = a4[base + i * 32 + lane];
        s += a.x * b.x + a.y * b.y + a.z * b.z + a.w * b.w;
    }
    s = warp_sum(s);

    __shared__ float part[4];
    if (lane == 0) part[warp] = s;
    __syncthreads();
    if (lane == 0 && half == 0)
        out[r] = part[warp] + part[warp + 1];
}

// ------------------------- launch -------------------------------------------
extern "C" void kernel_launch(void* const* d_in, const int* in_sizes, int n_in,
                              void* d_out, int out_size) {
    const float* x       = (const float*)d_in[0];
    // d_in[1] = kv_sliding (unused by reference math)
    float*       kv_full = (float*)d_in[2];
    const float* wq      = (const float*)d_in[3];
    const float* wk      = (const float*)d_in[4];
    const float* wv      = (const float*)d_in[5];
    const float* wo      = (const float*)d_in[6];
    const int*   curpos  = (const int*)d_in[7];
    // d_in[8] = ring_pos (unused)
    float* out = (float*)d_out;

    qkv_gemv<<<1280, 128>>>(x, wq, wk, wv, kv_full, curpos);
    attn_chunk<<<NCHUNK, 256>>>(kv_full);
    reduce_final<<<128, 256>>>();
    wo_gemv<<<1280, 128>>>(wo, out);
}